// round 8
// baseline (speedup 1.0000x reference)
#include <cuda_runtime.h>
#include <cstdint>

#define B_DIM 32
#define S_LEN 2048
#define I_DIM 256
#define H_DIM 256

// ---------------------------------------------------------------------------
// helpers
// ---------------------------------------------------------------------------
__device__ __forceinline__ unsigned long long ffma2(unsigned long long a,
                                                    unsigned long long b,
                                                    unsigned long long c) {
    unsigned long long d;
    asm("fma.rn.f32x2 %0, %1, %2, %3;" : "=l"(d) : "l"(a), "l"(b), "l"(c));
    return d;
}
__device__ __forceinline__ unsigned long long pack2(float x, float y) {
    unsigned long long d;
    asm("mov.b64 %0, {%1, %2};" : "=l"(d) : "f"(x), "f"(y));
    return d;
}
__device__ __forceinline__ float2 unpack2(unsigned long long v) {
    float2 r;
    asm("mov.b64 {%0, %1}, %2;" : "=f"(r.x), "=f"(r.y) : "l"(v));
    return r;
}
__device__ __forceinline__ uint32_t smem_u32(const void* p) {
    uint32_t a;
    asm("{ .reg .u64 t; cvta.to.shared.u64 t, %1; cvt.u32.u64 %0, t; }"
        : "=r"(a) : "l"(p));
    return a;
}
__device__ __forceinline__ uint32_t mapa_u32(uint32_t a, uint32_t rank) {
    uint32_t d;
    asm("mapa.shared::cluster.u32 %0, %1, %2;" : "=r"(d) : "r"(a), "r"(rank));
    return d;
}
__device__ __forceinline__ void mbar_init(uint32_t mbar, uint32_t count) {
    asm volatile("mbarrier.init.shared.b64 [%0], %1;" :: "r"(mbar), "r"(count) : "memory");
}
__device__ __forceinline__ void mbar_arrive(uint32_t mbar) {
    asm volatile("mbarrier.arrive.shared.b64 _, [%0];" :: "r"(mbar) : "memory");
}
__device__ __forceinline__ void mbar_expect_tx(uint32_t mbar, uint32_t bytes) {
    asm volatile("mbarrier.arrive.expect_tx.shared.b64 _, [%0], %1;"
                 :: "r"(mbar), "r"(bytes) : "memory");
}
// sleeping wait (fallback / ordering fast-path)
__device__ __forceinline__ void mbar_wait(uint32_t mbar, uint32_t parity) {
    asm volatile(
        "{\n\t.reg .pred P;\n\t"
        "WL%=:\n\t"
        "mbarrier.try_wait.parity.acquire.cta.shared::cta.b64 P, [%0], %1, 0x989680;\n\t"
        "@!P bra WL%=;\n\t}"
        :: "r"(mbar), "r"(parity) : "memory");
}
// raw read of the mbarrier word's phase bit (bit63) — cheap non-sleeping poll
__device__ __forceinline__ uint32_t mbar_phase_bit(uint32_t mbar) {
    uint32_t lo, hi;
    asm volatile("ld.volatile.shared.v2.u32 {%0, %1}, [%2];"
                 : "=r"(lo), "=r"(hi) : "r"(mbar));
    return hi & 0x80000000u;
}
__device__ __forceinline__ void st_async_b64(uint32_t raddr, unsigned long long v,
                                             uint32_t rmbar) {
    asm volatile(
        "st.async.shared::cluster.mbarrier::complete_tx::bytes.b64 [%0], %1, [%2];"
        :: "r"(raddr), "l"(v), "r"(rmbar) : "memory");
}
__device__ __forceinline__ float tanh_fast(float x) {
    float r;
    asm("tanh.approx.f32 %0, %1;" : "=f"(r) : "f"(x));
    return r;
}

// ---------------------------------------------------------------------------
// Kernel 1: xw[b,s,h] = x[b,s,:] . Wx_w[h,:] + Wx_b[h]  (into outputs region)
// ---------------------------------------------------------------------------
__global__ __launch_bounds__(256, 2)
void xw_gemm_kernel(const float* __restrict__ A, const float* __restrict__ W,
                    const float* __restrict__ bias, float* __restrict__ C) {
    __shared__ __align__(16) float As[16][128];
    __shared__ __align__(16) float Bs[16][128];

    const int tid = threadIdx.x;
    const int tx = tid & 15;
    const int ty = tid >> 4;
    const long bm = (long)blockIdx.x * 128;
    const long bn = (long)blockIdx.y * 128;

    const float* Ab = A + bm * I_DIM;
    const float* Wb = W + bn * I_DIM;

    unsigned long long acc[8][4];
#pragma unroll
    for (int i = 0; i < 8; i++)
#pragma unroll
        for (int j = 0; j < 4; j++) acc[i][j] = 0ull;

    for (int k0 = 0; k0 < I_DIM; k0 += 16) {
#pragma unroll
        for (int f = tid; f < 512; f += 256) {
            int row = f >> 2, kq = f & 3;
            float4 va = *(const float4*)(Ab + (long)row * I_DIM + k0 + kq * 4);
            As[kq * 4 + 0][row] = va.x; As[kq * 4 + 1][row] = va.y;
            As[kq * 4 + 2][row] = va.z; As[kq * 4 + 3][row] = va.w;
            float4 vw = *(const float4*)(Wb + (long)row * I_DIM + k0 + kq * 4);
            Bs[kq * 4 + 0][row] = vw.x; Bs[kq * 4 + 1][row] = vw.y;
            Bs[kq * 4 + 2][row] = vw.z; Bs[kq * 4 + 3][row] = vw.w;
        }
        __syncthreads();
#pragma unroll
        for (int k = 0; k < 16; k++) {
            const float4* As4 = (const float4*)&As[k][0];
            const ulonglong2* Bs2 = (const ulonglong2*)&Bs[k][0];
            float4 a0 = As4[ty * 2], a1 = As4[ty * 2 + 1];
            ulonglong2 bA = Bs2[tx * 2], bB = Bs2[tx * 2 + 1];
            unsigned long long bp[4] = {bA.x, bA.y, bB.x, bB.y};
            float av[8] = {a0.x, a0.y, a0.z, a0.w, a1.x, a1.y, a1.z, a1.w};
#pragma unroll
            for (int i = 0; i < 8; i++) {
                unsigned long long ap = pack2(av[i], av[i]);
#pragma unroll
                for (int j = 0; j < 4; j++) acc[i][j] = ffma2(ap, bp[j], acc[i][j]);
            }
        }
        __syncthreads();
    }

    float bv[8];
#pragma unroll
    for (int j = 0; j < 8; j++) bv[j] = bias[bn + tx * 8 + j];
#pragma unroll
    for (int i = 0; i < 8; i++) {
        long m = bm + ty * 8 + i;
        float* Crow = C + m * (long)H_DIM + bn + tx * 8;
        float2 c0 = unpack2(acc[i][0]), c1 = unpack2(acc[i][1]);
        float2 c2 = unpack2(acc[i][2]), c3 = unpack2(acc[i][3]);
        *(float4*)(Crow)     = make_float4(c0.x + bv[0], c0.y + bv[1], c1.x + bv[2], c1.y + bv[3]);
        *(float4*)(Crow + 4) = make_float4(c2.x + bv[4], c2.y + bv[5], c3.x + bv[6], c3.y + bv[7]);
    }
}

// ---------------------------------------------------------------------------
// Kernel 2: recurrence (R5 structure, 1674us baseline) with SPIN-WAIT:
// the sleeping try_wait is replaced by a raw volatile-LDS poll of the
// mbarrier phase bit (bit63), then one guaranteed-fast-path try_wait.acquire
// for ordering. Expected phase bits self-calibrated at startup; 4096-poll cap
// falls back to the sleeping wait (correct even if bit convention differs).
// ---------------------------------------------------------------------------
__global__ __launch_bounds__(256, 1) __cluster_dims__(2, 1, 1)
void srnn_recur_kernel(const float* __restrict__ Wh, float* __restrict__ out) {
    __shared__ __align__(16) float hL[2][128];   // my half (local STS)
    __shared__ __align__(16) float hR[2][128];   // peer half (st.async dst)
    __shared__ __align__(8) unsigned long long mbar[2];

    const int rank = blockIdx.x;
    const int row  = blockIdx.y;
    const int t    = threadIdx.x;
    const int jl   = t >> 1;          // 0..127 local output index
    const int kc   = t & 1;           // 0..1 k-chunk (64 k per half each)
    const int jg   = rank * 128 + jl;

    // --- preload 128 weights: 64 local-half + 64 remote-half ---
    unsigned long long wlA[16], wlB[16], wrA[16], wrB[16];
    {
        const float* wL = Wh + (long)jg * H_DIM + (rank * 128 + kc * 64);
        const float* wR = Wh + (long)jg * H_DIM + ((rank ^ 1) * 128 + kc * 64);
#pragma unroll
        for (int u = 0; u < 16; u++) {
            ulonglong2 a = *(const ulonglong2*)(wL + u * 4);
            wlA[u] = a.x; wlB[u] = a.y;
            ulonglong2 b = *(const ulonglong2*)(wR + u * 4);
            wrA[u] = b.x; wrB[u] = b.y;
        }
    }

    const uint32_t mb0 = smem_u32(&mbar[0]);
    const uint32_t mb1 = smem_u32(&mbar[1]);

    if (t == 0) {
        mbar_init(mb0, 1);
        mbar_init(mb1, 1);
        mbar_arrive(mb0);            // mbar[0] phase 0: trivially complete (h0 = 0)
        mbar_expect_tx(mb1, 512);    // armed for peer's step-0 sends (-> hR[1])
    }
    if (t < 128) { hL[0][t] = 0.0f; hR[0][t] = 0.0f; }
    __syncthreads();

    // Sample expected phase bits BEFORE the cluster barrier (peer cannot have
    // sent yet -> no race). mb0's phase 0 already completed (arrive above), so
    // exp0 == current bit (step-0 spin passes instantly); mb1 flips on its
    // step-0 completion, so expect the inverse.
    uint32_t exp0 = mbar_phase_bit(mb0);
    uint32_t exp1 = mbar_phase_bit(mb1) ^ 0x80000000u;

    asm volatile("barrier.cluster.arrive.aligned;" ::: "memory");
    asm volatile("barrier.cluster.wait.aligned;" ::: "memory");

    const uint32_t prB0 = mapa_u32(smem_u32(&hR[0][0]), rank ^ 1);
    const uint32_t prB1 = mapa_u32(smem_u32(&hR[1][0]), rank ^ 1);
    const uint32_t pmb0 = mapa_u32(mb0, rank ^ 1);
    const uint32_t pmb1 = mapa_u32(mb1, rank ^ 1);

    // kc==1 lanes with even jl ship the pair {v_jl, v_jl+1}
    const bool shipper = (kc == 1) && ((jl & 1) == 0);
    const uint32_t shipoff = (uint32_t)jl * 4u;

    float* xwp = out + (long)row * S_LEN * H_DIM + jg;
    float xw_next = xwp[0];

    for (int step = 0; step < S_LEN; step++) {
        const int p = step & 1;
        float xw_cur = xw_next;
        if (step + 1 < S_LEN)
            xw_next = xwp[(long)(step + 1) * H_DIM];

        unsigned long long a0 = 0ull, a1 = 0ull, a2 = 0ull, a3 = 0ull;

        // ---- local half (hL[p] visible from last step's __syncthreads)
        {
            const ulonglong2* h2 = (const ulonglong2*)&hL[p][kc * 64];
#pragma unroll
            for (int u = 0; u < 16; u += 2) {
                ulonglong2 h0 = h2[u], h1 = h2[u + 1];
                a0 = ffma2(h0.x, wlA[u], a0);
                a1 = ffma2(h0.y, wlB[u], a1);
                a2 = ffma2(h1.x, wlA[u + 1], a2);
                a3 = ffma2(h1.y, wlB[u + 1], a3);
            }
        }

        // ---- SPIN-wait for peer half (no sleep), then fast-path acquire;
        //      re-arm this mbar for step+2
        {
            const uint32_t mb   = p ? mb1 : mb0;
            const uint32_t expb = p ? exp1 : exp0;
            int polls = 0;
            while (mbar_phase_bit(mb) != expb && polls < 4096) polls++;
            mbar_wait(mb, (step >> 1) & 1);   // completes instantly; acquire order
            if (p) exp1 ^= 0x80000000u; else exp0 ^= 0x80000000u;
            if (t == 3) mbar_expect_tx(mb, 512);
        }

        // ---- remote half
        {
            const ulonglong2* h2 = (const ulonglong2*)&hR[p][kc * 64];
#pragma unroll
            for (int u = 0; u < 16; u += 2) {
                ulonglong2 h0 = h2[u], h1 = h2[u + 1];
                a0 = ffma2(h0.x, wrA[u], a0);
                a1 = ffma2(h0.y, wrB[u], a1);
                a2 = ffma2(h1.x, wrA[u + 1], a2);
                a3 = ffma2(h1.y, wrB[u + 1], a3);
            }
        }

        float2 f0 = unpack2(a0), f1 = unpack2(a1);
        float2 f2 = unpack2(a2), f3 = unpack2(a3);
        float s = ((f0.x + f0.y) + (f1.x + f1.y)) +
                  ((f2.x + f2.y) + (f3.x + f3.y));
        s += __shfl_xor_sync(0xffffffffu, s, 1);   // both kc lanes: full sum

        float v   = tanh_fast(s + xw_cur);
        float vhi = __shfl_down_sync(0xffffffffu, v, 2);   // jl+1's value

        if (shipper) {
            st_async_b64((p ? prB0 : prB1) + shipoff, pack2(v, vhi),
                         p ? pmb0 : pmb1);
        } else if (kc == 0) {
            hL[p ^ 1][jl] = v;                    // local half STS
            xwp[(long)step * H_DIM] = v;          // in-place output
        }
        if (kc == 1 && step == S_LEN - 1)
            out[(long)B_DIM * S_LEN * H_DIM + (long)row * H_DIM + jg] = v;

        __syncthreads();
    }

    asm volatile("barrier.cluster.arrive.aligned;" ::: "memory");
    asm volatile("barrier.cluster.wait.aligned;" ::: "memory");
}

// ---------------------------------------------------------------------------
// Launch
// ---------------------------------------------------------------------------
extern "C" void kernel_launch(void* const* d_in, const int* in_sizes, int n_in,
                              void* d_out, int out_size) {
    const float* x    = (const float*)d_in[0];  // [B,S,I]
    const float* Wx_w = (const float*)d_in[1];  // [H,I]
    const float* Wx_b = (const float*)d_in[2];  // [H]
    const float* Wh_w = (const float*)d_in[3];  // [H,H]
    float* out = (float*)d_out;                 // [B,S,H] ++ [B,H]

    dim3 g1((B_DIM * S_LEN) / 128, H_DIM / 128);
    xw_gemm_kernel<<<g1, 256>>>(x, Wx_w, Wx_b, out);

    dim3 g2(2, B_DIM);
    srnn_recur_kernel<<<g2, 256>>>(Wh_w, out);
}

// round 9
// speedup vs baseline: 64.4604x; 64.4604x over previous
#include <cuda_runtime.h>
#include <cstdint>

#define B_DIM 32
#define S_LEN 2048
#define I_DIM 256
#define H_DIM 256

// ---------------------------------------------------------------------------
// helpers
// ---------------------------------------------------------------------------
__device__ __forceinline__ unsigned long long ffma2(unsigned long long a,
                                                    unsigned long long b,
                                                    unsigned long long c) {
    unsigned long long d;
    asm("fma.rn.f32x2 %0, %1, %2, %3;" : "=l"(d) : "l"(a), "l"(b), "l"(c));
    return d;
}
__device__ __forceinline__ unsigned long long pack2(float x, float y) {
    unsigned long long d;
    asm("mov.b64 %0, {%1, %2};" : "=l"(d) : "f"(x), "f"(y));
    return d;
}
__device__ __forceinline__ float2 unpack2(unsigned long long v) {
    float2 r;
    asm("mov.b64 {%0, %1}, %2;" : "=f"(r.x), "=f"(r.y) : "l"(v));
    return r;
}
__device__ __forceinline__ uint32_t smem_u32(const void* p) {
    uint32_t a;
    asm("{ .reg .u64 t; cvta.to.shared.u64 t, %1; cvt.u32.u64 %0, t; }"
        : "=r"(a) : "l"(p));
    return a;
}
__device__ __forceinline__ uint32_t mapa_u32(uint32_t a, uint32_t rank) {
    uint32_t d;
    asm("mapa.shared::cluster.u32 %0, %1, %2;" : "=r"(d) : "r"(a), "r"(rank));
    return d;
}
__device__ __forceinline__ void mbar_init(uint32_t mbar, uint32_t count) {
    asm volatile("mbarrier.init.shared.b64 [%0], %1;" :: "r"(mbar), "r"(count) : "memory");
}
__device__ __forceinline__ void mbar_expect_tx(uint32_t mbar, uint32_t bytes) {
    asm volatile("mbarrier.arrive.expect_tx.shared.b64 _, [%0], %1;"
                 :: "r"(mbar), "r"(bytes) : "memory");
}
__device__ __forceinline__ void mbar_wait(uint32_t mbar, uint32_t parity) {
    asm volatile(
        "{\n\t.reg .pred P;\n\t"
        "WL%=:\n\t"
        "mbarrier.try_wait.parity.acquire.cta.shared::cta.b64 P, [%0], %1, 0x989680;\n\t"
        "@!P bra WL%=;\n\t}"
        :: "r"(mbar), "r"(parity) : "memory");
}
__device__ __forceinline__ void st_async_b64(uint32_t raddr, unsigned long long v,
                                             uint32_t rmbar) {
    asm volatile(
        "st.async.shared::cluster.mbarrier::complete_tx::bytes.b64 [%0], %1, [%2];"
        :: "r"(raddr), "l"(v), "r"(rmbar) : "memory");
}
__device__ __forceinline__ float tanh_fast(float x) {
    float r;
    asm("tanh.approx.f32 %0, %1;" : "=f"(r) : "f"(x));
    return r;
}

// ---------------------------------------------------------------------------
// Kernel 1: xw[b,s,h] = x[b,s,:] . Wx_w[h,:] + Wx_b[h]  (into outputs region)
// ---------------------------------------------------------------------------
__global__ __launch_bounds__(256, 2)
void xw_gemm_kernel(const float* __restrict__ A, const float* __restrict__ W,
                    const float* __restrict__ bias, float* __restrict__ C) {
    __shared__ __align__(16) float As[16][128];
    __shared__ __align__(16) float Bs[16][128];

    const int tid = threadIdx.x;
    const int tx = tid & 15;
    const int ty = tid >> 4;
    const long bm = (long)blockIdx.x * 128;
    const long bn = (long)blockIdx.y * 128;

    const float* Ab = A + bm * I_DIM;
    const float* Wb = W + bn * I_DIM;

    unsigned long long acc[8][4];
#pragma unroll
    for (int i = 0; i < 8; i++)
#pragma unroll
        for (int j = 0; j < 4; j++) acc[i][j] = 0ull;

    for (int k0 = 0; k0 < I_DIM; k0 += 16) {
#pragma unroll
        for (int f = tid; f < 512; f += 256) {
            int row = f >> 2, kq = f & 3;
            float4 va = *(const float4*)(Ab + (long)row * I_DIM + k0 + kq * 4);
            As[kq * 4 + 0][row] = va.x; As[kq * 4 + 1][row] = va.y;
            As[kq * 4 + 2][row] = va.z; As[kq * 4 + 3][row] = va.w;
            float4 vw = *(const float4*)(Wb + (long)row * I_DIM + k0 + kq * 4);
            Bs[kq * 4 + 0][row] = vw.x; Bs[kq * 4 + 1][row] = vw.y;
            Bs[kq * 4 + 2][row] = vw.z; Bs[kq * 4 + 3][row] = vw.w;
        }
        __syncthreads();
#pragma unroll
        for (int k = 0; k < 16; k++) {
            const float4* As4 = (const float4*)&As[k][0];
            const ulonglong2* Bs2 = (const ulonglong2*)&Bs[k][0];
            float4 a0 = As4[ty * 2], a1 = As4[ty * 2 + 1];
            ulonglong2 bA = Bs2[tx * 2], bB = Bs2[tx * 2 + 1];
            unsigned long long bp[4] = {bA.x, bA.y, bB.x, bB.y};
            float av[8] = {a0.x, a0.y, a0.z, a0.w, a1.x, a1.y, a1.z, a1.w};
#pragma unroll
            for (int i = 0; i < 8; i++) {
                unsigned long long ap = pack2(av[i], av[i]);
#pragma unroll
                for (int j = 0; j < 4; j++) acc[i][j] = ffma2(ap, bp[j], acc[i][j]);
            }
        }
        __syncthreads();
    }

    float bv[8];
#pragma unroll
    for (int j = 0; j < 8; j++) bv[j] = bias[bn + tx * 8 + j];
#pragma unroll
    for (int i = 0; i < 8; i++) {
        long m = bm + ty * 8 + i;
        float* Crow = C + m * (long)H_DIM + bn + tx * 8;
        float2 c0 = unpack2(acc[i][0]), c1 = unpack2(acc[i][1]);
        float2 c2 = unpack2(acc[i][2]), c3 = unpack2(acc[i][3]);
        *(float4*)(Crow)     = make_float4(c0.x + bv[0], c0.y + bv[1], c1.x + bv[2], c1.y + bv[3]);
        *(float4*)(Crow + 4) = make_float4(c2.x + bv[4], c2.y + bv[5], c3.x + bv[6], c3.y + bv[7]);
    }
}

// ---------------------------------------------------------------------------
// Kernel 2: recurrence with PARTIAL-SUM exchange.
// 2-CTA cluster per batch row, 256 threads, thread (jl 0..127, kc 0..1).
// Weights in regs: wP = Wh[peer output jl][my k-half]   (64 floats)
//                  wL = Wh[my   output jl][my k-half]   (64 floats)
// Per step: (1) compute PEER partial from local h, reduce, ship (64 b64);
//           (2) compute LOCAL partial, reduce (overlaps transit);
//           (3) wait mbar, v = tanh(L + pbuf[jl] + xw), STS h, bar.
// The remote-side FMAs are gone from the post-wait critical path.
// ---------------------------------------------------------------------------
__global__ __launch_bounds__(256, 1) __cluster_dims__(2, 1, 1)
void srnn_recur_kernel(const float* __restrict__ Wh, float* __restrict__ out) {
    __shared__ __align__(16) float hS[2][128];     // my h half
    __shared__ __align__(16) float pbuf[2][128];   // peer partials (st.async dst)
    __shared__ __align__(8) unsigned long long mbar[2];

    const int rank = blockIdx.x;
    const int row  = blockIdx.y;
    const int t    = threadIdx.x;
    const int jl   = t >> 1;          // 0..127
    const int kc   = t & 1;           // 0..1 (64 k each within my half)
    const int jg   = rank * 128 + jl;             // my output
    const int jp   = (rank ^ 1) * 128 + jl;       // peer output I help with

    // --- preload weights: peer-output rows + my-output rows, my k-half ---
    unsigned long long wPA[16], wPB[16], wLA[16], wLB[16];
    {
        const float* wp = Wh + (long)jp * H_DIM + (rank * 128 + kc * 64);
        const float* wl = Wh + (long)jg * H_DIM + (rank * 128 + kc * 64);
#pragma unroll
        for (int u = 0; u < 16; u++) {
            ulonglong2 a = *(const ulonglong2*)(wp + u * 4);
            wPA[u] = a.x; wPB[u] = a.y;
            ulonglong2 b = *(const ulonglong2*)(wl + u * 4);
            wLA[u] = b.x; wLB[u] = b.y;
        }
    }

    const uint32_t mb0 = smem_u32(&mbar[0]);
    const uint32_t mb1 = smem_u32(&mbar[1]);

    if (t == 0) {
        mbar_init(mb0, 1);
        mbar_init(mb1, 1);
        mbar_expect_tx(mb0, 512);    // armed for step-0 partial exchange
        mbar_expect_tx(mb1, 512);    // armed for step-1
    }
    if (t < 128) hS[0][t] = 0.0f;    // h0 = 0
    __syncthreads();
    asm volatile("barrier.cluster.arrive.aligned;" ::: "memory");
    asm volatile("barrier.cluster.wait.aligned;" ::: "memory");

    const uint32_t prB0 = mapa_u32(smem_u32(&pbuf[0][0]), rank ^ 1);
    const uint32_t prB1 = mapa_u32(smem_u32(&pbuf[1][0]), rank ^ 1);
    const uint32_t pmb0 = mapa_u32(mb0, rank ^ 1);
    const uint32_t pmb1 = mapa_u32(mb1, rank ^ 1);

    // kc==0 lanes with even jl ship the pair {P_jl, P_jl+1} (64 x 8B = 512B)
    const bool shipper = (kc == 0) && ((jl & 1) == 0);
    const uint32_t shipoff = (uint32_t)jl * 4u;

    float* xwp = out + (long)row * S_LEN * H_DIM + jg;
    float xw_next = xwp[0];

    for (int step = 0; step < S_LEN; step++) {
        const int b = step & 1;
        float xw_cur = xw_next;
        if (step + 1 < S_LEN)
            xw_next = xwp[(long)(step + 1) * H_DIM];

        const ulonglong2* h2 = (const ulonglong2*)&hS[b][kc * 64];

        // ---- (1) PEER partial: ship ASAP ----
        unsigned long long p0 = 0ull, p1 = 0ull, p2 = 0ull, p3 = 0ull;
#pragma unroll
        for (int u = 0; u < 16; u += 2) {
            ulonglong2 hv0 = h2[u], hv1 = h2[u + 1];
            p0 = ffma2(hv0.x, wPA[u], p0);
            p1 = ffma2(hv0.y, wPB[u], p1);
            p2 = ffma2(hv1.x, wPA[u + 1], p2);
            p3 = ffma2(hv1.y, wPB[u + 1], p3);
        }
        float2 g0 = unpack2(p0), g1 = unpack2(p1);
        float2 g2 = unpack2(p2), g3 = unpack2(p3);
        float P = ((g0.x + g0.y) + (g1.x + g1.y)) +
                  ((g2.x + g2.y) + (g3.x + g3.y));
        P += __shfl_xor_sync(0xffffffffu, P, 1);          // sum over kc
        float Phi = __shfl_down_sync(0xffffffffu, P, 2);  // jl+1's P

        if (shipper)
            st_async_b64((b ? prB1 : prB0) + shipoff, pack2(P, Phi),
                         b ? pmb1 : pmb0);

        // ---- (2) LOCAL partial (overlaps the transit) ----
        unsigned long long a0 = 0ull, a1 = 0ull, a2 = 0ull, a3 = 0ull;
#pragma unroll
        for (int u = 0; u < 16; u += 2) {
            ulonglong2 hv0 = h2[u], hv1 = h2[u + 1];
            a0 = ffma2(hv0.x, wLA[u], a0);
            a1 = ffma2(hv0.y, wLB[u], a1);
            a2 = ffma2(hv1.x, wLA[u + 1], a2);
            a3 = ffma2(hv1.y, wLB[u + 1], a3);
        }
        float2 f0 = unpack2(a0), f1 = unpack2(a1);
        float2 f2 = unpack2(a2), f3 = unpack2(a3);
        float L = ((f0.x + f0.y) + (f1.x + f1.y)) +
                  ((f2.x + f2.y) + (f3.x + f3.y));
        L += __shfl_xor_sync(0xffffffffu, L, 1);

        // ---- (3) wait for peer's partials, finish the step ----
        mbar_wait(b ? mb1 : mb0, (step >> 1) & 1);
        if (t == 3) mbar_expect_tx(b ? mb1 : mb0, 512);   // re-arm for step+2

        float v = tanh_fast(L + pbuf[b][jl] + xw_cur);

        if (kc == 0) {
            hS[b ^ 1][jl] = v;                    // next h (my half)
        } else {
            xwp[(long)step * H_DIM] = v;          // in-place output
            if (step == S_LEN - 1)
                out[(long)B_DIM * S_LEN * H_DIM + (long)row * H_DIM + jg] = v;
        }

        __syncthreads();   // hS[b^1] visible; pbuf[b]/hS[b] reads done
    }

    asm volatile("barrier.cluster.arrive.aligned;" ::: "memory");
    asm volatile("barrier.cluster.wait.aligned;" ::: "memory");
}

// ---------------------------------------------------------------------------
// Launch
// ---------------------------------------------------------------------------
extern "C" void kernel_launch(void* const* d_in, const int* in_sizes, int n_in,
                              void* d_out, int out_size) {
    const float* x    = (const float*)d_in[0];  // [B,S,I]
    const float* Wx_w = (const float*)d_in[1];  // [H,I]
    const float* Wx_b = (const float*)d_in[2];  // [H]
    const float* Wh_w = (const float*)d_in[3];  // [H,H]
    float* out = (float*)d_out;                 // [B,S,H] ++ [B,H]

    dim3 g1((B_DIM * S_LEN) / 128, H_DIM / 128);
    xw_gemm_kernel<<<g1, 256>>>(x, Wx_w, Wx_b, out);

    dim3 g2(2, B_DIM);
    srnn_recur_kernel<<<g2, 256>>>(Wh_w, out);
}